// round 15
// baseline (speedup 1.0000x reference)
#include <cuda_runtime.h>
#include <cuda_fp16.h>
#include <math.h>
#include <stdint.h>

#define NTOK 16384
#define CDIM 8192
#define HDIM 2048
#define IDIM 8192

// Scratch (allocation-free rule: __device__ globals)
__device__ __align__(256) float g_h[(size_t)CDIM * IDIM];      // silu(g)*u
__device__ __align__(256) float g_down[(size_t)CDIM * HDIM];

// ---------------------------------------------------------------------------
// helpers (plain sm_80-era PTX only)
// ---------------------------------------------------------------------------
__device__ __forceinline__ uint32_t smem_u32(const void* p) {
    return (uint32_t)__cvta_generic_to_shared(p);
}
__device__ __forceinline__ void ldsm4(uint32_t a, uint32_t* r) {
    asm volatile("ldmatrix.sync.aligned.m8n8.x4.shared.b16 {%0,%1,%2,%3}, [%4];"
                 : "=r"(r[0]), "=r"(r[1]), "=r"(r[2]), "=r"(r[3]) : "r"(a));
}
// fp16 x fp16 -> fp32 accum MMA
__device__ __forceinline__ void hmma(float* c, const uint32_t* a,
                                     uint32_t b0, uint32_t b1) {
    asm volatile(
        "mma.sync.aligned.m16n8k16.row.col.f32.f16.f16.f32 "
        "{%0,%1,%2,%3},{%4,%5,%6,%7},{%8,%9},{%0,%1,%2,%3};"
        : "+f"(c[0]), "+f"(c[1]), "+f"(c[2]), "+f"(c[3])
        : "r"(a[0]), "r"(a[1]), "r"(a[2]), "r"(a[3]), "r"(b0), "r"(b1));
}
// fp32x4 -> fp16x4 (8B)
__device__ __forceinline__ uint2 cvt4h(float4 v) {
    __half2 a = __floats2half2_rn(v.x, v.y);
    __half2 b = __floats2half2_rn(v.z, v.w);
    return make_uint2(*reinterpret_cast<uint32_t*>(&a),
                      *reinterpret_cast<uint32_t*>(&b));
}
__device__ __forceinline__ float silu(float g) { return g / (1.f + __expf(-g)); }

// smem rows: 32 fp16 padded to 40 (80B = 5x16B) — conflict-free ldmatrix
#define ROWB 80
// k1 planes: A(128r) | G(128r) | U(128r)
#define K1_G     10240
#define K1_U     20480
#define STAGE1   30720
#define SMEM1    (2 * STAGE1)   // 60 KB
// k2 planes: A(256r) | B(128r)
#define K2_B     20480
#define STAGE2   30720
#define SMEM2    (2 * STAGE2)   // 60 KB

#define NC1 (HDIM / 32)   // 64 chunks
#define NC2 (IDIM / 32)   // 256 chunks

// ---------------------------------------------------------------------------
// Kernel 1: gather + dual GEMM (gate,up) + SiLU. CTA 128m x 128n (both mats).
// 8 warps of 64x64: warps 0-3 gate (2m x 2n), warps 4-7 up. Pure fp16 MMA.
// ---------------------------------------------------------------------------
__global__ __launch_bounds__(256, 1)
void k1_gateup(const float* __restrict__ x,
               const float* __restrict__ Wg,
               const float* __restrict__ Wu,
               const int* __restrict__ fg)
{
    extern __shared__ __align__(128) char sm[];
    const uint32_t smb = smem_u32(sm);
    const int tid  = threadIdx.x;
    const int wid  = tid >> 5;
    const int lane = tid & 31;
    const int m0 = blockIdx.x * 128;   // m fastest -> B tiles L2-resident
    const int n0 = blockIdx.y * 128;

    // staging: 8 threads/row, one float4 each, 4 rows/thread per matrix
    const int rbase = tid >> 3;
    const int c4    = (tid & 7) * 4;
    const float *pA[4], *pG[4], *pU[4];
    int sts[4];
#pragma unroll
    for (int j = 0; j < 4; j++) {
        int row = rbase + 32 * j;
        pA[j] = x  + (size_t)__ldg(fg + m0 + row) * HDIM + c4;
        pG[j] = Wg + (size_t)(n0 + row) * HDIM + c4;
        pU[j] = Wu + (size_t)(n0 + row) * HDIM + c4;
        sts[j] = row * ROWB + (tid & 7) * 8;
    }

    // ldmatrix lane geometry; warp tile 64x64
    const int laneRow = ((lane >> 3) & 1) * 8 + (lane & 7);
    const int laneK   = (lane >> 4) * 16;
    const int wg  = wid & 3;
    const int R   = 64 * (wg >> 1);
    const int Cw  = 64 * (wg & 1);
    const int bSec = (wid >= 4) ? K1_U : K1_G;

    float acc[4][8][4];
#pragma unroll
    for (int f = 0; f < 4; f++)
#pragma unroll
        for (int n = 0; n < 8; n++)
#pragma unroll
            for (int q = 0; q < 4; q++) acc[f][n][q] = 0.f;

    // prologue: chunk 0 -> buf 0
    float4 rA[4], rG[4], rU[4];
#pragma unroll
    for (int j = 0; j < 4; j++) {
        rA[j] = *reinterpret_cast<const float4*>(pA[j]);
        rG[j] = *reinterpret_cast<const float4*>(pG[j]);
        rU[j] = *reinterpret_cast<const float4*>(pU[j]);
    }
#pragma unroll
    for (int j = 0; j < 4; j++) {
        *reinterpret_cast<uint2*>(sm + sts[j])        = cvt4h(rA[j]);
        *reinterpret_cast<uint2*>(sm + K1_G + sts[j]) = cvt4h(rG[j]);
        *reinterpret_cast<uint2*>(sm + K1_U + sts[j]) = cvt4h(rU[j]);
    }

#pragma unroll 1
    for (int c = 0; c < NC1; c++) {
        __syncthreads();
        if (c + 1 < NC1) {
            const int k0 = (c + 1) * 32;
#pragma unroll
            for (int j = 0; j < 4; j++) {
                rA[j] = *reinterpret_cast<const float4*>(pA[j] + k0);
                rG[j] = *reinterpret_cast<const float4*>(pG[j] + k0);
                rU[j] = *reinterpret_cast<const float4*>(pU[j] + k0);
            }
        }
        const uint32_t sb = smb + (uint32_t)(c & 1) * STAGE1;
#pragma unroll
        for (int s = 0; s < 2; s++) {
            const uint32_t ab = sb + (uint32_t)((R + laneRow) * ROWB + laneK + 32 * s);
            uint32_t a[4][4];
#pragma unroll
            for (int f = 0; f < 4; f++)
                ldsm4(ab + (uint32_t)(16 * f * ROWB), a[f]);
#pragma unroll
            for (int gp = 0; gp < 4; gp++) {
                const uint32_t bb = sb + (uint32_t)(bSec +
                    (Cw + 16 * gp + laneRow) * ROWB + laneK + 32 * s);
                uint32_t b[4];
                ldsm4(bb, b);
#pragma unroll
                for (int f = 0; f < 4; f++)
#pragma unroll
                    for (int h = 0; h < 2; h++)
                        hmma(acc[f][2 * gp + h], a[f], b[h], b[2 + h]);
            }
        }
        if (c + 1 < NC1) {
            char* nb = sm + (size_t)((c + 1) & 1) * STAGE1;
#pragma unroll
            for (int j = 0; j < 4; j++) {
                *reinterpret_cast<uint2*>(nb + sts[j])        = cvt4h(rA[j]);
                *reinterpret_cast<uint2*>(nb + K1_G + sts[j]) = cvt4h(rG[j]);
                *reinterpret_cast<uint2*>(nb + K1_U + sts[j]) = cvt4h(rU[j]);
            }
        }
    }

    // ---- epilogue: two 32-row phases; up warps park, gate warps combine ----
    float* upbuf = reinterpret_cast<float*>(sm);   // 4 x (32 x 68) floats
#pragma unroll 1
    for (int half = 0; half < 2; half++) {
        __syncthreads();
        if (wid >= 4) {
            float* base = upbuf + (wid - 4) * 2176;
#pragma unroll
            for (int fi = 0; fi < 2; fi++)
#pragma unroll
                for (int n = 0; n < 8; n++) {
                    const float* a = acc[2 * half + fi][n];
                    int row = 16 * fi + (lane >> 2);
                    int col = 8 * n + (lane & 3) * 2;
                    float* b0 = base + row * 68 + col;
                    b0[0] = a[0]; b0[1] = a[1];
                    float* b1 = b0 + 8 * 68;
                    b1[0] = a[2]; b1[1] = a[3];
                }
        }
        __syncthreads();
        if (wid < 4) {
            const float* base = upbuf + wid * 2176;
#pragma unroll
            for (int fi = 0; fi < 2; fi++)
#pragma unroll
                for (int n = 0; n < 8; n++) {
                    const float* a = acc[2 * half + fi][n];
                    int row = 16 * fi + (lane >> 2);
                    int col = 8 * n + (lane & 3) * 2;
                    const float* b0 = base + row * 68 + col;
                    const float* b1 = b0 + 8 * 68;
                    int grow = m0 + R + 32 * half + row;
                    float* o0 = g_h + (size_t)grow * IDIM + n0 + Cw + col;
                    float* o1 = o0 + (size_t)8 * IDIM;
                    *reinterpret_cast<float2*>(o0) =
                        make_float2(silu(a[0]) * b0[0], silu(a[1]) * b0[1]);
                    *reinterpret_cast<float2*>(o1) =
                        make_float2(silu(a[2]) * b1[0], silu(a[3]) * b1[1]);
                }
        }
    }
}

// ---------------------------------------------------------------------------
// Kernel 2: down projection. CTA 256m x 128n, 8 warps 4m x 2n of 64x64.
// ---------------------------------------------------------------------------
__global__ __launch_bounds__(256, 1)
void k2_down(const float* __restrict__ Wd)
{
    extern __shared__ __align__(128) char sm[];
    const uint32_t smb = smem_u32(sm);
    const int tid  = threadIdx.x;
    const int wid  = tid >> 5;
    const int lane = tid & 31;
    const int m0 = blockIdx.x * 256;   // m fastest -> Wd stays L2-resident
    const int n0 = blockIdx.y * 128;

    // A staging: 1 thread/row (256 rows), 8 float4 each
    const float* pA = g_h + (size_t)(m0 + tid) * IDIM;
    const int stsA = tid * ROWB;
    // B staging: 2 threads/row (128 rows), 4 float4 each
    const int brow = tid >> 1;
    const float* pB = Wd + (size_t)(n0 + brow) * IDIM + (tid & 1) * 16;
    const int stsB = brow * ROWB + (tid & 1) * 32;

    const int laneRow = ((lane >> 3) & 1) * 8 + (lane & 7);
    const int laneK   = (lane >> 4) * 16;
    const int R   = 64 * (wid & 3);
    const int Cw  = 64 * (wid >> 2);

    float acc[4][8][4];
#pragma unroll
    for (int f = 0; f < 4; f++)
#pragma unroll
        for (int n = 0; n < 8; n++)
#pragma unroll
            for (int q = 0; q < 4; q++) acc[f][n][q] = 0.f;

    float4 rA[8], rB[4];
#pragma unroll
    for (int j = 0; j < 8; j++)
        rA[j] = *reinterpret_cast<const float4*>(pA + 4 * j);
#pragma unroll
    for (int j = 0; j < 4; j++)
        rB[j] = *reinterpret_cast<const float4*>(pB + 4 * j);
#pragma unroll
    for (int j = 0; j < 8; j++)
        *reinterpret_cast<uint2*>(sm + stsA + 8 * j) = cvt4h(rA[j]);
#pragma unroll
    for (int j = 0; j < 4; j++)
        *reinterpret_cast<uint2*>(sm + K2_B + stsB + 8 * j) = cvt4h(rB[j]);

#pragma unroll 1
    for (int c = 0; c < NC2; c++) {
        __syncthreads();
        if (c + 1 < NC2) {
            const int k0 = (c + 1) * 32;
#pragma unroll
            for (int j = 0; j < 8; j++)
                rA[j] = *reinterpret_cast<const float4*>(pA + k0 + 4 * j);
#pragma unroll
            for (int j = 0; j < 4; j++)
                rB[j] = *reinterpret_cast<const float4*>(pB + k0 + 4 * j);
        }
        const uint32_t sb = smb + (uint32_t)(c & 1) * STAGE2;
#pragma unroll
        for (int s = 0; s < 2; s++) {
            const uint32_t ab = sb + (uint32_t)((R + laneRow) * ROWB + laneK + 32 * s);
            uint32_t a[4][4];
#pragma unroll
            for (int f = 0; f < 4; f++)
                ldsm4(ab + (uint32_t)(16 * f * ROWB), a[f]);
#pragma unroll
            for (int gp = 0; gp < 4; gp++) {
                const uint32_t bb = sb + (uint32_t)(K2_B +
                    (Cw + 16 * gp + laneRow) * ROWB + laneK + 32 * s);
                uint32_t b[4];
                ldsm4(bb, b);
#pragma unroll
                for (int f = 0; f < 4; f++)
#pragma unroll
                    for (int h = 0; h < 2; h++)
                        hmma(acc[f][2 * gp + h], a[f], b[h], b[2 + h]);
            }
        }
        if (c + 1 < NC2) {
            char* nb = sm + (size_t)((c + 1) & 1) * STAGE2;
#pragma unroll
            for (int j = 0; j < 8; j++)
                *reinterpret_cast<uint2*>(nb + stsA + 8 * j) = cvt4h(rA[j]);
#pragma unroll
            for (int j = 0; j < 4; j++)
                *reinterpret_cast<uint2*>(nb + K2_B + stsB + 8 * j) = cvt4h(rB[j]);
        }
    }

    // epilogue: direct fp32 stores
#pragma unroll
    for (int f = 0; f < 4; f++)
#pragma unroll
        for (int n = 0; n < 8; n++) {
            int row = m0 + R + 16 * f + (lane >> 2);
            int col = n0 + Cw + 8 * n + (lane & 3) * 2;
            float* o0 = g_down + (size_t)row * HDIM + col;
            float* o1 = o0 + (size_t)8 * HDIM;
            *reinterpret_cast<float2*>(o0) = make_float2(acc[f][n][0], acc[f][n][1]);
            *reinterpret_cast<float2*>(o1) = make_float2(acc[f][n][2], acc[f][n][3]);
        }
}

// ---------------------------------------------------------------------------
// Kernel 3: scatter
// ---------------------------------------------------------------------------
__global__ __launch_bounds__(256)
void scatter_kernel(const int* __restrict__ scatter_indices,
                    float* __restrict__ out)
{
    const int t = blockIdx.x;
    const int c = scatter_indices[t];
    const float4* src = reinterpret_cast<const float4*>(g_down + (size_t)c * HDIM);
    float4*       dst = reinterpret_cast<float4*>(out + (size_t)t * HDIM);
#pragma unroll
    for (int j = threadIdx.x; j < HDIM / 4; j += 256)
        dst[j] = src[j];
}

// ---------------------------------------------------------------------------
extern "C" void kernel_launch(void* const* d_in, const int* in_sizes, int n_in,
                              void* d_out, int out_size)
{
    const float* x  = (const float*)d_in[0];
    const float* Wg = (const float*)d_in[1];
    const float* Wu = (const float*)d_in[2];
    const float* Wd = (const float*)d_in[3];
    const int*   fg = (const int*)d_in[4];
    const int*   sc = (const int*)d_in[5];
    float*       out = (float*)d_out;

    cudaFuncSetAttribute(k1_gateup, cudaFuncAttributeMaxDynamicSharedMemorySize, SMEM1);
    cudaFuncSetAttribute(k2_down,   cudaFuncAttributeMaxDynamicSharedMemorySize, SMEM2);

    dim3 g1(CDIM / 128, IDIM / 128);   // (64 m fastest, 64 n)
    k1_gateup<<<g1, 256, SMEM1>>>(x, Wg, Wu, fg);

    dim3 g2(CDIM / 256, HDIM / 128);   // (32 m fastest, 16 n)
    k2_down<<<g2, 256, SMEM2>>>(Wd);

    scatter_kernel<<<NTOK, 256>>>(sc, out);
}